// round 14
// baseline (speedup 1.0000x reference)
#include <cuda_runtime.h>
#include <math.h>

#define T_SEQ 512
#define R_DIM 2048
#define I_DIM 256
#define O_DIM 256
#define B_DIM 32
#define LEAKF 0.3f

#define NB 128      // persistent blocks (<= SM count; 1/SM forced via smem)
#define RB 16       // reservoir rows per block (128 * 16 = 2048)

#define SMEM_GEMM  ((32 * 257 + 256 * 68) * 4)            // 102528 B
#define SMEM_RECUR ((R_DIM * RB + 8 * RB * B_DIM) * 4)    // 147456 B

// ---------------- device scratch (allocation-free contract) ----------------
__device__ float g_uproj[(size_t)T_SEQ * R_DIM * B_DIM];   // [t][r][b]
__device__ float g_states[(size_t)T_SEQ * R_DIM * B_DIM];  // [t][r][b]
__device__ float g_s0T[R_DIM * B_DIM];                     // [r][b]
__device__ unsigned int g_bar_count;
__device__ volatile unsigned int g_bar_gen;

// packed fp32x2 FMA (Blackwell): d = a*b + d on two packed fp32 lanes
#define FMA2(d, a, b) asm("fma.rn.f32x2 %0, %1, %2, %0;" : "+l"(d) : "l"(a), "l"(b))

// ---------------- Phase 0: transpose initial state to [r][b] ----------------
__global__ void s0T_kernel(const float* __restrict__ state) {
    int idx = blockIdx.x * blockDim.x + threadIdx.x;  // 65536
    int r = idx >> 5, b = idx & 31;
    g_s0T[idx] = state[(size_t)b * R_DIM + r];
}

// ---------------- Phase 1: uproj[t][r][b] = sum_i u[b][t][i]*W_in[r][i] + bias[r]
// grid (512 t, 32 r-tiles of 64), 256 threads
__global__ void __launch_bounds__(256) uproj_kernel(const float* __restrict__ u,
                                                    const float* __restrict__ W_in,
                                                    const float* __restrict__ bias) {
    extern __shared__ float sm[];
    float* us = sm;             // [32][257] padded
    float* ws = sm + 32 * 257;  // [256][68] transposed + padded (16B-aligned rows)
    const int t   = blockIdx.x;
    const int rt  = blockIdx.y * 64;
    const int tid = threadIdx.x;

    for (int idx = tid; idx < 32 * 256; idx += 256) {
        int b = idx >> 8, i = idx & 255;
        us[b * 257 + i] = u[((size_t)b * T_SEQ + t) * I_DIM + i];
    }
    for (int idx = tid; idx < 64 * 256; idx += 256) {
        int rl = idx >> 8, i = idx & 255;
        ws[i * 68 + rl] = W_in[(size_t)(rt + rl) * I_DIM + i];
    }
    __syncthreads();

    const int b = tid & 31, rg = tid >> 5;
    float acc[8];
#pragma unroll
    for (int p = 0; p < 8; p++) acc[p] = 0.0f;

#pragma unroll 4
    for (int k = 0; k < 256; k++) {
        float uv  = us[b * 257 + k];
        float4 w0 = *(const float4*)(ws + k * 68 + rg * 8);
        float4 w1 = *(const float4*)(ws + k * 68 + rg * 8 + 4);
        acc[0] += w0.x * uv; acc[1] += w0.y * uv;
        acc[2] += w0.z * uv; acc[3] += w0.w * uv;
        acc[4] += w1.x * uv; acc[5] += w1.y * uv;
        acc[6] += w1.z * uv; acc[7] += w1.w * uv;
    }
#pragma unroll
    for (int p = 0; p < 8; p++) {
        int r = rt + rg * 8 + p;
        g_uproj[((size_t)t * R_DIM + r) * B_DIM + b] = acc[p] + bias[r];
    }
}

// ---------------- Phase 2: 512-step recurrence (persistent, grid-synced) ----
// Block owns RB=16 rows. W^T tile (2048 x 16 = 128 KB) staged in smem ONCE.
// 8 warps split K (256 each); smem cross-warp reduction; leaky-tanh epilogue.
__global__ void __launch_bounds__(256, 1) recur_kernel(const float* __restrict__ W) {
    extern __shared__ float sm[];
    float* Wt  = sm;               // [2048][16] k-major, 64B rows
    float* red = sm + R_DIM * RB;  // [8 warps][16 r][32 b]

    const int tid  = threadIdx.x;
    const int w    = tid >> 5;
    const int lane = tid & 31;
    const int r0   = blockIdx.x * RB;
    const int kbase = w << 8;      // 256-wide K slice per warp

    // Stage W^T: Wt[k*16+q] = W[(r0+q)*2048 + k]  (coalesced global reads)
    for (int idx = tid; idx < RB * R_DIM; idx += 256) {
        int q = idx >> 11;
        int k = idx & 2047;
        Wt[k * RB + q] = W[(size_t)(r0 + q) * R_DIM + k];
    }
    __syncthreads();

    for (int t = 0; t < T_SEQ; t++) {
        const float* prev = (t == 0) ? g_s0T
                                     : (g_states + (size_t)(t - 1) * R_DIM * B_DIM);
        const float* sp = prev + (size_t)kbase * B_DIM + lane;
        const ulonglong2* wp = (const ulonglong2*)(Wt + kbase * RB);

        unsigned long long acc[8];
#pragma unroll
        for (int p = 0; p < 8; p++) acc[p] = 0ULL;

        // software-pipelined K loop: 8 state loads in flight
        float sv[8];
#pragma unroll
        for (int j = 0; j < 8; j++) sv[j] = __ldcg(sp + j * B_DIM);

        for (int kk = 0; kk < 256; kk += 8) {
            float svn[8];
            if (kk + 8 < 256) {
#pragma unroll
                for (int j = 0; j < 8; j++) svn[j] = __ldcg(sp + (kk + 8 + j) * B_DIM);
            }
#pragma unroll
            for (int j = 0; j < 8; j++) {
                unsigned long long pv;
                asm("mov.b64 %0, {%1, %1};" : "=l"(pv) : "r"(__float_as_uint(sv[j])));
                const ulonglong2* row = wp + (size_t)(kk + j) * 4;  // 64B per k row
                ulonglong2 a0 = row[0];
                ulonglong2 a1 = row[1];
                ulonglong2 a2 = row[2];
                ulonglong2 a3 = row[3];
                FMA2(acc[0], a0.x, pv); FMA2(acc[1], a0.y, pv);
                FMA2(acc[2], a1.x, pv); FMA2(acc[3], a1.y, pv);
                FMA2(acc[4], a2.x, pv); FMA2(acc[5], a2.y, pv);
                FMA2(acc[6], a3.x, pv); FMA2(acc[7], a3.y, pv);
            }
            if (kk + 8 < 256) {
#pragma unroll
                for (int j = 0; j < 8; j++) sv[j] = svn[j];
            }
        }

        // write per-warp partials (unpack f32x2 pairs)
#pragma unroll
        for (int p = 0; p < 8; p++) {
            unsigned int lo, hi;
            asm("mov.b64 {%0, %1}, %2;" : "=r"(lo), "=r"(hi) : "l"(acc[p]));
            red[(w * RB + 2 * p)     * B_DIM + lane] = __uint_as_float(lo);
            red[(w * RB + 2 * p + 1) * B_DIM + lane] = __uint_as_float(hi);
        }
        __syncthreads();

        // cross-warp reduce + leaky tanh epilogue: 512 outputs, 2 per thread
#pragma unroll
        for (int h = 0; h < 2; h++) {
            int idx = tid + h * 256;
            int q = idx >> 5, b = idx & 31;
            float sum = 0.0f;
#pragma unroll
            for (int ww = 0; ww < 8; ww++) sum += red[(ww * RB + q) * B_DIM + b];
            int r = r0 + q;
            float pre  = g_uproj[((size_t)t * R_DIM + r) * B_DIM + b] + sum;
            float sold = __ldcg(prev + (size_t)r * B_DIM + b);
            float snew = (1.0f - LEAKF) * sold + LEAKF * tanhf(pre);
            g_states[((size_t)t * R_DIM + r) * B_DIM + b] = snew;
        }

        // grid barrier (generation target = t+1; replay-safe, reset at exit)
        __syncthreads();
        if (tid == 0) {
            __threadfence();
            unsigned int target = (unsigned int)(t + 1);
            if (atomicAdd(&g_bar_count, 1u) == (unsigned int)(NB - 1)) {
                g_bar_count = 0u;
                __threadfence();
                g_bar_gen = target;
            } else {
                while (g_bar_gen < target) { }
            }
            __threadfence();
        }
        __syncthreads();
    }

    // final arrive: last block resets generation to 0 for the next graph replay
    if (tid == 0) {
        __threadfence();
        if (atomicAdd(&g_bar_count, 1u) == (unsigned int)(NB - 1)) {
            g_bar_count = 0u;
            __threadfence();
            g_bar_gen = 0u;
        }
    }
}

// ---------------- Phase 3: out[b][t][o] = sum_r states[t][r][b]*w_ro[o][r] + b_ro[o]
// grid (512 t, 4 o-tiles of 64), 256 threads, K chunked by 256
__global__ void __launch_bounds__(256) readout_kernel(const float* __restrict__ w_ro,
                                                      const float* __restrict__ b_ro,
                                                      float* __restrict__ out) {
    extern __shared__ float sm[];
    float* ss = sm;             // [32][257]
    float* wt = sm + 32 * 257;  // [256][68]
    const int t   = blockIdx.x;
    const int ot  = blockIdx.y * 64;
    const int tid = threadIdx.x;
    const int b = tid & 31, og = tid >> 5;

    float acc[8];
#pragma unroll
    for (int p = 0; p < 8; p++) acc[p] = 0.0f;

    for (int c = 0; c < R_DIM; c += 256) {
        for (int idx = tid; idx < 32 * 256; idx += 256) {
            int k = idx >> 5, bb = idx & 31;
            ss[bb * 257 + k] = g_states[((size_t)t * R_DIM + c + k) * B_DIM + bb];
        }
        for (int idx = tid; idx < 64 * 256; idx += 256) {
            int ol = idx >> 8, k = idx & 255;
            wt[k * 68 + ol] = w_ro[(size_t)(ot + ol) * R_DIM + c + k];
        }
        __syncthreads();

#pragma unroll 4
        for (int k = 0; k < 256; k++) {
            float sv  = ss[b * 257 + k];
            float4 w0 = *(const float4*)(wt + k * 68 + og * 8);
            float4 w1 = *(const float4*)(wt + k * 68 + og * 8 + 4);
            acc[0] += w0.x * sv; acc[1] += w0.y * sv;
            acc[2] += w0.z * sv; acc[3] += w0.w * sv;
            acc[4] += w1.x * sv; acc[5] += w1.y * sv;
            acc[6] += w1.z * sv; acc[7] += w1.w * sv;
        }
        __syncthreads();
    }

#pragma unroll
    for (int p = 0; p < 8; p++) {
        int o = ot + og * 8 + p;
        out[((size_t)b * T_SEQ + t) * O_DIM + o] = acc[p] + b_ro[o];
    }
}

// ---------------- launch ----------------
extern "C" void kernel_launch(void* const* d_in, const int* in_sizes, int n_in,
                              void* d_out, int out_size) {
    (void)in_sizes; (void)n_in; (void)out_size;
    const float* u     = (const float*)d_in[0];  // (32, 512, 256)
    const float* state = (const float*)d_in[1];  // (32, 2048)
    const float* W_in  = (const float*)d_in[2];  // (2048, 256)
    const float* W     = (const float*)d_in[3];  // (2048, 2048)
    const float* bias  = (const float*)d_in[4];  // (2048,)
    const float* w_ro  = (const float*)d_in[5];  // (256, 2048)
    const float* b_ro  = (const float*)d_in[6];  // (256,)
    float* out = (float*)d_out;                  // (32, 512, 256)

    cudaFuncSetAttribute(uproj_kernel,   cudaFuncAttributeMaxDynamicSharedMemorySize, SMEM_GEMM);
    cudaFuncSetAttribute(readout_kernel, cudaFuncAttributeMaxDynamicSharedMemorySize, SMEM_GEMM);
    cudaFuncSetAttribute(recur_kernel,   cudaFuncAttributeMaxDynamicSharedMemorySize, SMEM_RECUR);

    s0T_kernel<<<256, 256>>>(state);
    uproj_kernel<<<dim3(T_SEQ, R_DIM / 64), 256, SMEM_GEMM>>>(u, W_in, bias);
    recur_kernel<<<NB, 256, SMEM_RECUR>>>(W);
    readout_kernel<<<dim3(T_SEQ, O_DIM / 64), 256, SMEM_GEMM>>>(w_ro, b_ro, out);
}

// round 15
// speedup vs baseline: 1.1822x; 1.1822x over previous
#include <cuda_runtime.h>
#include <math.h>

#define T_SEQ 512
#define R_DIM 2048
#define I_DIM 256
#define O_DIM 256
#define B_DIM 32
#define LEAKF 0.3f

#define NB 128      // persistent blocks (1/SM forced via smem)
#define RB 16       // reservoir rows per block
#define RTH 512     // recurrence threads (16 warps)
#define KSL 128     // k per warp slice (2048/16)

#define SMEM_GEMM  ((256 * 68 + 32 * 257) * 4)            // 102528 B
#define SMEM_RECUR ((R_DIM * RB + 16 * RB * B_DIM) * 4)   // 163840 B

// ---------------- device scratch (allocation-free contract) ----------------
__device__ float g_uproj[(size_t)T_SEQ * R_DIM * B_DIM];   // [t][r][b]
__device__ float g_states[(size_t)T_SEQ * R_DIM * B_DIM];  // [t][r][b]
__device__ float g_s0T[R_DIM * B_DIM];                     // [r][b]
__device__ unsigned int g_bar_count;
__device__ volatile unsigned int g_bar_gen;

// packed fp32x2 FMA (Blackwell FFMA2): d = a*b + d on two packed fp32 lanes
#define FMA2(d, a, b) asm("fma.rn.f32x2 %0, %1, %2, %0;" : "+l"(d) : "l"(a), "l"(b))
#define PACK2(pv, x)  asm("mov.b64 %0, {%1, %1};" : "=l"(pv) : "r"(__float_as_uint(x)))

// ---------------- Phase 0: transpose initial state to [r][b] ----------------
__global__ void s0T_kernel(const float* __restrict__ state) {
    int idx = blockIdx.x * blockDim.x + threadIdx.x;  // 65536
    int r = idx >> 5, b = idx & 31;
    g_s0T[idx] = state[(size_t)b * R_DIM + r];
}

// ---------------- Phase 1: uproj[t][r][b] = sum_i u[b][t][i]*W_in[r][i] + bias[r]
// grid (64 t-tiles of 8, 32 r-tiles of 64), 256 threads. W_in tile staged once per block.
__global__ void __launch_bounds__(256) uproj_kernel(const float* __restrict__ u,
                                                    const float* __restrict__ W_in,
                                                    const float* __restrict__ bias) {
    extern __shared__ float sm[];
    float* ws = sm;             // [256][68] transposed + padded (16B-aligned rows)
    float* us = sm + 256 * 68;  // [32][257]
    const int t0  = blockIdx.x * 8;
    const int rt  = blockIdx.y * 64;
    const int tid = threadIdx.x;
    const int b = tid & 31, rg = tid >> 5;

    for (int idx = tid; idx < 64 * 256; idx += 256) {
        int rl = idx >> 8, i = idx & 255;
        ws[i * 68 + rl] = W_in[(size_t)(rt + rl) * I_DIM + i];
    }

    float bs[8];
#pragma unroll
    for (int p = 0; p < 8; p++) bs[p] = bias[rt + rg * 8 + p];

    for (int tt = 0; tt < 8; tt++) {
        const int t = t0 + tt;
        __syncthreads();  // covers ws at tt=0, protects us reuse after
        for (int idx = tid; idx < 32 * 256; idx += 256) {
            int bb = idx >> 8, i = idx & 255;
            us[bb * 257 + i] = u[((size_t)bb * T_SEQ + t) * I_DIM + i];
        }
        __syncthreads();

        unsigned long long acc[4] = {0ULL, 0ULL, 0ULL, 0ULL};
#pragma unroll 4
        for (int k = 0; k < 256; k++) {
            unsigned long long pv; PACK2(pv, us[b * 257 + k]);
            const ulonglong2* wp = (const ulonglong2*)(ws + k * 68 + rg * 8);
            ulonglong2 w0 = wp[0], w1 = wp[1];
            FMA2(acc[0], w0.x, pv); FMA2(acc[1], w0.y, pv);
            FMA2(acc[2], w1.x, pv); FMA2(acc[3], w1.y, pv);
        }
#pragma unroll
        for (int p = 0; p < 4; p++) {
            unsigned int lo, hi;
            asm("mov.b64 {%0, %1}, %2;" : "=r"(lo), "=r"(hi) : "l"(acc[p]));
            int r = rt + rg * 8 + 2 * p;
            g_uproj[((size_t)t * R_DIM + r)     * B_DIM + b] = __uint_as_float(lo) + bs[2 * p];
            g_uproj[((size_t)t * R_DIM + r + 1) * B_DIM + b] = __uint_as_float(hi) + bs[2 * p + 1];
        }
    }
}

// ---------------- Phase 2: 512-step recurrence (persistent, grid-synced) ----
// Each block owns RB=16 rows; W^T tile (2048x16 = 128 KB) staged in smem once.
// 16 warps split K (128 each) with per-block (slice, rotation) skew so the 128
// lock-stepped blocks never pile onto the same L2 line (LTS hotspot fix).
__device__ __forceinline__ void gemv_run(const float* __restrict__ sp,   // prev + kbase*32 + lane
                                         const float* __restrict__ wt,   // Wt + kbase*16
                                         int klo, int khi,
                                         unsigned long long* acc) {
    float sv[8];
#pragma unroll
    for (int j = 0; j < 8; j++) sv[j] = __ldcg(sp + (klo + j) * B_DIM);
    for (int kk = klo; kk < khi; kk += 8) {
        const int nk = kk + 8;
        float svn[8];
        if (nk < khi) {
#pragma unroll
            for (int j = 0; j < 8; j++) svn[j] = __ldcg(sp + (nk + j) * B_DIM);
        }
#pragma unroll
        for (int j = 0; j < 8; j++) {
            unsigned long long pv; PACK2(pv, sv[j]);
            const ulonglong2* row = (const ulonglong2*)(wt + (size_t)(kk + j) * RB);
            ulonglong2 a0 = row[0], a1 = row[1], a2 = row[2], a3 = row[3];
            FMA2(acc[0], a0.x, pv); FMA2(acc[1], a0.y, pv);
            FMA2(acc[2], a1.x, pv); FMA2(acc[3], a1.y, pv);
            FMA2(acc[4], a2.x, pv); FMA2(acc[5], a2.y, pv);
            FMA2(acc[6], a3.x, pv); FMA2(acc[7], a3.y, pv);
        }
        if (nk < khi) {
#pragma unroll
            for (int j = 0; j < 8; j++) sv[j] = svn[j];
        }
    }
}

__global__ void __launch_bounds__(RTH, 1) recur_kernel(const float* __restrict__ W) {
    extern __shared__ float sm[];
    float* Wt  = sm;               // [2048][16] k-major rows of 64 B
    float* red = sm + R_DIM * RB;  // [16 warps][16 r][32 b]

    const int tid  = threadIdx.x;
    const int w    = tid >> 5;
    const int lane = tid & 31;
    const int blk  = blockIdx.x;
    const int r0   = blk * RB;
    const int slice = (w + blk) & 15;            // per-block warp-slice permutation
    const int rot   = ((blk >> 4) & 7) * 16;     // per-block intra-slice rotation
    const int kbase = slice * KSL;

    // Stage W^T: Wt[k*16+q] = W[(r0+q)*2048 + k]
    for (int idx = tid; idx < RB * R_DIM; idx += RTH) {
        int q = idx >> 11, k = idx & 2047;
        Wt[k * RB + q] = W[(size_t)(r0 + q) * R_DIM + k];
    }
    __syncthreads();

    const int eq = tid >> 5;   // epilogue row 0..15
    const int eb = lane;       // epilogue batch

    for (int t = 0; t < T_SEQ; t++) {
        const float* prev = (t == 0) ? g_s0T
                                     : (g_states + (size_t)(t - 1) * R_DIM * B_DIM);

        // prefetch epilogue operands early (latency hidden behind the K loop)
        float up = __ldcg(&g_uproj[((size_t)t * R_DIM + r0 + eq) * B_DIM + eb]);
        float so = __ldcg(&prev[(size_t)(r0 + eq) * B_DIM + eb]);

        unsigned long long acc[8] = {0ULL,0ULL,0ULL,0ULL,0ULL,0ULL,0ULL,0ULL};
        const float* sp = prev + (size_t)kbase * B_DIM + lane;
        const float* wb = Wt + (size_t)kbase * RB;
        gemv_run(sp, wb, rot, KSL, acc);
        if (rot > 0) gemv_run(sp, wb, 0, rot, acc);

#pragma unroll
        for (int p = 0; p < 8; p++) {
            unsigned int lo, hi;
            asm("mov.b64 {%0, %1}, %2;" : "=r"(lo), "=r"(hi) : "l"(acc[p]));
            red[(w * RB + 2 * p)     * B_DIM + lane] = __uint_as_float(lo);
            red[(w * RB + 2 * p + 1) * B_DIM + lane] = __uint_as_float(hi);
        }
        __syncthreads();

        float sum = 0.0f;
#pragma unroll
        for (int ww = 0; ww < 16; ww++) sum += red[(ww * RB + eq) * B_DIM + eb];
        float pre  = up + sum;
        float snew = (1.0f - LEAKF) * so + LEAKF * tanhf(pre);
        g_states[((size_t)t * R_DIM + r0 + eq) * B_DIM + eb] = snew;

        // grid barrier (generation target = t+1; replay-safe)
        __syncthreads();
        if (tid == 0) {
            __threadfence();
            unsigned int target = (unsigned int)(t + 1);
            if (atomicAdd(&g_bar_count, 1u) == (unsigned int)(NB - 1)) {
                g_bar_count = 0u;
                __threadfence();
                g_bar_gen = target;
            } else {
                while (g_bar_gen < target) { }
            }
            __threadfence();
        }
        __syncthreads();
    }

    // final arrive: last block resets generation to 0 for the next graph replay
    if (tid == 0) {
        __threadfence();
        if (atomicAdd(&g_bar_count, 1u) == (unsigned int)(NB - 1)) {
            g_bar_count = 0u;
            __threadfence();
            g_bar_gen = 0u;
        }
    }
}

// ---------------- Phase 3: out[b][t][o] = sum_r states[t][r][b]*w_ro[o][r] + b_ro[o]
// grid (128 t-tiles of 4, 4 o-tiles of 64), 256 threads; w_ro tile reused across 4 t.
__global__ void __launch_bounds__(256) readout_kernel(const float* __restrict__ w_ro,
                                                      const float* __restrict__ b_ro,
                                                      float* __restrict__ out) {
    extern __shared__ float sm[];
    float* wt = sm;             // [256][68]
    float* ss = sm + 256 * 68;  // [32][257]
    const int t0  = blockIdx.x * 4;
    const int ot  = blockIdx.y * 64;
    const int tid = threadIdx.x;
    const int b = tid & 31, og = tid >> 5;

    unsigned long long acc[4][4];
#pragma unroll
    for (int tt = 0; tt < 4; tt++)
#pragma unroll
        for (int p = 0; p < 4; p++) acc[tt][p] = 0ULL;

    for (int c = 0; c < R_DIM; c += 256) {
        __syncthreads();  // protect wt/ss reuse
        for (int idx = tid; idx < 64 * 256; idx += 256) {
            int ol = idx >> 8, k = idx & 255;
            wt[k * 68 + ol] = w_ro[(size_t)(ot + ol) * R_DIM + c + k];
        }
        for (int tt = 0; tt < 4; tt++) {
            const int t = t0 + tt;
            __syncthreads();  // ss reuse (and wt ready at tt=0)
            for (int idx = tid; idx < 32 * 256; idx += 256) {
                int k = idx >> 5, bb = idx & 31;
                ss[bb * 257 + k] = g_states[((size_t)t * R_DIM + c + k) * B_DIM + bb];
            }
            __syncthreads();
#pragma unroll 4
            for (int k = 0; k < 256; k++) {
                unsigned long long pv; PACK2(pv, ss[b * 257 + k]);
                const ulonglong2* wp = (const ulonglong2*)(wt + k * 68 + og * 8);
                ulonglong2 w0 = wp[0], w1 = wp[1];
                FMA2(acc[tt][0], w0.x, pv); FMA2(acc[tt][1], w0.y, pv);
                FMA2(acc[tt][2], w1.x, pv); FMA2(acc[tt][3], w1.y, pv);
            }
        }
    }

    float bo[8];
#pragma unroll
    for (int p = 0; p < 8; p++) bo[p] = b_ro[ot + og * 8 + p];

#pragma unroll
    for (int tt = 0; tt < 4; tt++) {
        const int t = t0 + tt;
#pragma unroll
        for (int p = 0; p < 4; p++) {
            unsigned int lo, hi;
            asm("mov.b64 {%0, %1}, %2;" : "=r"(lo), "=r"(hi) : "l"(acc[tt][p]));
            int o = ot + og * 8 + 2 * p;
            out[((size_t)b * T_SEQ + t) * O_DIM + o]     = __uint_as_float(lo) + bo[2 * p];
            out[((size_t)b * T_SEQ + t) * O_DIM + o + 1] = __uint_as_float(hi) + bo[2 * p + 1];
        }
    }
}

// ---------------- launch ----------------
extern "C" void kernel_launch(void* const* d_in, const int* in_sizes, int n_in,
                              void* d_out, int out_size) {
    (void)in_sizes; (void)n_in; (void)out_size;
    const float* u     = (const float*)d_in[0];  // (32, 512, 256)
    const float* state = (const float*)d_in[1];  // (32, 2048)
    const float* W_in  = (const float*)d_in[2];  // (2048, 256)
    const float* W     = (const float*)d_in[3];  // (2048, 2048)
    const float* bias  = (const float*)d_in[4];  // (2048,)
    const float* w_ro  = (const float*)d_in[5];  // (256, 2048)
    const float* b_ro  = (const float*)d_in[6];  // (256,)
    float* out = (float*)d_out;                  // (32, 512, 256)

    cudaFuncSetAttribute(uproj_kernel,   cudaFuncAttributeMaxDynamicSharedMemorySize, SMEM_GEMM);
    cudaFuncSetAttribute(readout_kernel, cudaFuncAttributeMaxDynamicSharedMemorySize, SMEM_GEMM);
    cudaFuncSetAttribute(recur_kernel,   cudaFuncAttributeMaxDynamicSharedMemorySize, SMEM_RECUR);

    s0T_kernel<<<256, 256>>>(state);
    uproj_kernel<<<dim3(T_SEQ / 8, R_DIM / 64), 256, SMEM_GEMM>>>(u, W_in, bias);
    recur_kernel<<<NB, RTH, SMEM_RECUR>>>(W);
    readout_kernel<<<dim3(T_SEQ / 4, O_DIM / 64), 256, SMEM_GEMM>>>(w_ro, b_ro, out);
}

// round 17
// speedup vs baseline: 1.1834x; 1.0010x over previous
#include <cuda_runtime.h>
#include <math.h>

#define T_SEQ 512
#define R_DIM 2048
#define I_DIM 256
#define O_DIM 256
#define B_DIM 32
#define LEAKF 0.3f

#define NB 128      // persistent blocks (1/SM forced via smem)
#define RB 16       // reservoir rows per block
#define RTH 512     // recurrence threads (16 warps)
#define KSL 128     // k per warp slice (2048/16)

#define SMEM_GEMM  ((256 * 68 + 32 * 257) * 4)            // 102528 B
#define SMEM_RECUR ((R_DIM * RB + 16 * RB * B_DIM) * 4)   // 163840 B

// ---------------- device scratch (allocation-free contract) ----------------
__device__ float g_uproj[(size_t)T_SEQ * R_DIM * B_DIM];   // [t][r][b]
__device__ float g_states[(size_t)T_SEQ * R_DIM * B_DIM];  // [t][r][b]
__device__ float g_s0T[R_DIM * B_DIM];                     // [r][b]
__device__ unsigned int g_bar_count;
__device__ volatile unsigned int g_bar_gen;

// packed fp32x2 FMA (Blackwell FFMA2): d = a*b + d on two packed fp32 lanes
#define FMA2(d, a, b) asm("fma.rn.f32x2 %0, %1, %2, %0;" : "+l"(d) : "l"(a), "l"(b))
#define PACK2(pv, x)  asm("mov.b64 %0, {%1, %1};" : "=l"(pv) : "r"(__float_as_uint(x)))

// ---------------- Phase 0: transpose initial state to [r][b] ----------------
__global__ void s0T_kernel(const float* __restrict__ state) {
    int idx = blockIdx.x * blockDim.x + threadIdx.x;  // 65536
    int r = idx >> 5, b = idx & 31;
    g_s0T[idx] = state[(size_t)b * R_DIM + r];
}

// ---------------- Phase 1: uproj[t][r][b] = sum_i u[b][t][i]*W_in[r][i] + bias[r]
// grid (64 t-tiles of 8, 32 r-tiles of 64), 256 threads. W_in tile staged once per block.
__global__ void __launch_bounds__(256) uproj_kernel(const float* __restrict__ u,
                                                    const float* __restrict__ W_in,
                                                    const float* __restrict__ bias) {
    extern __shared__ float sm[];
    float* ws = sm;             // [256][68] transposed + padded (16B-aligned rows)
    float* us = sm + 256 * 68;  // [32][257]
    const int t0  = blockIdx.x * 8;
    const int rt  = blockIdx.y * 64;
    const int tid = threadIdx.x;
    const int b = tid & 31, rg = tid >> 5;

    for (int idx = tid; idx < 64 * 256; idx += 256) {
        int rl = idx >> 8, i = idx & 255;
        ws[i * 68 + rl] = W_in[(size_t)(rt + rl) * I_DIM + i];
    }

    float bs[8];
#pragma unroll
    for (int p = 0; p < 8; p++) bs[p] = bias[rt + rg * 8 + p];

    for (int tt = 0; tt < 8; tt++) {
        const int t = t0 + tt;
        __syncthreads();  // covers ws at tt=0, protects us reuse after
        for (int idx = tid; idx < 32 * 256; idx += 256) {
            int bb = idx >> 8, i = idx & 255;
            us[bb * 257 + i] = u[((size_t)bb * T_SEQ + t) * I_DIM + i];
        }
        __syncthreads();

        unsigned long long acc[4] = {0ULL, 0ULL, 0ULL, 0ULL};
#pragma unroll 4
        for (int k = 0; k < 256; k++) {
            unsigned long long pv; PACK2(pv, us[b * 257 + k]);
            const ulonglong2* wp = (const ulonglong2*)(ws + k * 68 + rg * 8);
            ulonglong2 w0 = wp[0], w1 = wp[1];
            FMA2(acc[0], w0.x, pv); FMA2(acc[1], w0.y, pv);
            FMA2(acc[2], w1.x, pv); FMA2(acc[3], w1.y, pv);
        }
#pragma unroll
        for (int p = 0; p < 4; p++) {
            unsigned int lo, hi;
            asm("mov.b64 {%0, %1}, %2;" : "=r"(lo), "=r"(hi) : "l"(acc[p]));
            int r = rt + rg * 8 + 2 * p;
            g_uproj[((size_t)t * R_DIM + r)     * B_DIM + b] = __uint_as_float(lo) + bs[2 * p];
            g_uproj[((size_t)t * R_DIM + r + 1) * B_DIM + b] = __uint_as_float(hi) + bs[2 * p + 1];
        }
    }
}

// ---------------- Phase 2: 512-step recurrence (persistent, grid-synced) ----
// Each block owns RB=16 rows; W^T tile (2048x16 = 128 KB) staged in smem once.
// 16 warps split K (128 each) with per-block (slice, rotation) skew so the 128
// lock-stepped blocks never pile onto the same L2 line (LTS hotspot fix).
__device__ __forceinline__ void gemv_run(const float* __restrict__ sp,   // prev + kbase*32 + lane
                                         const float* __restrict__ wt,   // Wt + kbase*16
                                         int klo, int khi,
                                         unsigned long long* acc) {
    float sv[8];
#pragma unroll
    for (int j = 0; j < 8; j++) sv[j] = __ldcg(sp + (klo + j) * B_DIM);
    for (int kk = klo; kk < khi; kk += 8) {
        const int nk = kk + 8;
        float svn[8];
        if (nk < khi) {
#pragma unroll
            for (int j = 0; j < 8; j++) svn[j] = __ldcg(sp + (nk + j) * B_DIM);
        }
#pragma unroll
        for (int j = 0; j < 8; j++) {
            unsigned long long pv; PACK2(pv, sv[j]);
            const ulonglong2* row = (const ulonglong2*)(wt + (size_t)(kk + j) * RB);
            ulonglong2 a0 = row[0], a1 = row[1], a2 = row[2], a3 = row[3];
            FMA2(acc[0], a0.x, pv); FMA2(acc[1], a0.y, pv);
            FMA2(acc[2], a1.x, pv); FMA2(acc[3], a1.y, pv);
            FMA2(acc[4], a2.x, pv); FMA2(acc[5], a2.y, pv);
            FMA2(acc[6], a3.x, pv); FMA2(acc[7], a3.y, pv);
        }
        if (nk < khi) {
#pragma unroll
            for (int j = 0; j < 8; j++) sv[j] = svn[j];
        }
    }
}

__global__ void __launch_bounds__(RTH, 1) recur_kernel(const float* __restrict__ W) {
    extern __shared__ float sm[];
    float* Wt  = sm;               // [2048][16] k-major rows of 64 B
    float* red = sm + R_DIM * RB;  // [16 warps][16 r][32 b]

    const int tid  = threadIdx.x;
    const int w    = tid >> 5;
    const int lane = tid & 31;
    const int blk  = blockIdx.x;
    const int r0   = blk * RB;
    const int slice = (w + blk) & 15;            // per-block warp-slice permutation
    const int rot   = ((blk >> 4) & 7) * 16;     // per-block intra-slice rotation
    const int kbase = slice * KSL;

    // Stage W^T: Wt[k*16+q] = W[(r0+q)*2048 + k]
    for (int idx = tid; idx < RB * R_DIM; idx += RTH) {
        int q = idx >> 11, k = idx & 2047;
        Wt[k * RB + q] = W[(size_t)(r0 + q) * R_DIM + k];
    }
    __syncthreads();

    const int eq = tid >> 5;   // epilogue row 0..15
    const int eb = lane;       // epilogue batch

    for (int t = 0; t < T_SEQ; t++) {
        const float* prev = (t == 0) ? g_s0T
                                     : (g_states + (size_t)(t - 1) * R_DIM * B_DIM);

        // prefetch epilogue operands early (latency hidden behind the K loop)
        float up = __ldcg(&g_uproj[((size_t)t * R_DIM + r0 + eq) * B_DIM + eb]);
        float so = __ldcg(&prev[(size_t)(r0 + eq) * B_DIM + eb]);

        unsigned long long acc[8] = {0ULL,0ULL,0ULL,0ULL,0ULL,0ULL,0ULL,0ULL};
        const float* sp = prev + (size_t)kbase * B_DIM + lane;
        const float* wb = Wt + (size_t)kbase * RB;
        gemv_run(sp, wb, rot, KSL, acc);
        if (rot > 0) gemv_run(sp, wb, 0, rot, acc);

#pragma unroll
        for (int p = 0; p < 8; p++) {
            unsigned int lo, hi;
            asm("mov.b64 {%0, %1}, %2;" : "=r"(lo), "=r"(hi) : "l"(acc[p]));
            red[(w * RB + 2 * p)     * B_DIM + lane] = __uint_as_float(lo);
            red[(w * RB + 2 * p + 1) * B_DIM + lane] = __uint_as_float(hi);
        }
        __syncthreads();

        float sum = 0.0f;
#pragma unroll
        for (int ww = 0; ww < 16; ww++) sum += red[(ww * RB + eq) * B_DIM + eb];
        float pre  = up + sum;
        float snew = (1.0f - LEAKF) * so + LEAKF * tanhf(pre);
        g_states[((size_t)t * R_DIM + r0 + eq) * B_DIM + eb] = snew;

        // grid barrier (generation target = t+1; replay-safe)
        __syncthreads();
        if (tid == 0) {
            __threadfence();
            unsigned int target = (unsigned int)(t + 1);
            if (atomicAdd(&g_bar_count, 1u) == (unsigned int)(NB - 1)) {
                g_bar_count = 0u;
                __threadfence();
                g_bar_gen = target;
            } else {
                while (g_bar_gen < target) { }
            }
            __threadfence();
        }
        __syncthreads();
    }

    // final arrive: last block resets generation to 0 for the next graph replay
    if (tid == 0) {
        __threadfence();
        if (atomicAdd(&g_bar_count, 1u) == (unsigned int)(NB - 1)) {
            g_bar_count = 0u;
            __threadfence();
            g_bar_gen = 0u;
        }
    }
}

// ---------------- Phase 3: out[b][t][o] = sum_r states[t][r][b]*w_ro[o][r] + b_ro[o]
// grid (128 t-tiles of 4, 4 o-tiles of 64), 256 threads; w_ro tile reused across 4 t.
__global__ void __launch_bounds__(256) readout_kernel(const float* __restrict__ w_ro,
                                                      const float* __restrict__ b_ro,
                                                      float* __restrict__ out) {
    extern __shared__ float sm[];
    float* wt = sm;             // [256][68]
    float* ss = sm + 256 * 68;  // [32][257]
    const int t0  = blockIdx.x * 4;
    const int ot  = blockIdx.y * 64;
    const int tid = threadIdx.x;
    const int b = tid & 31, og = tid >> 5;

    unsigned long long acc[4][4];
#pragma unroll
    for (int tt = 0; tt < 4; tt++)
#pragma unroll
        for (int p = 0; p < 4; p++) acc[tt][p] = 0ULL;

    for (int c = 0; c < R_DIM; c += 256) {
        __syncthreads();  // protect wt/ss reuse
        for (int idx = tid; idx < 64 * 256; idx += 256) {
            int ol = idx >> 8, k = idx & 255;
            wt[k * 68 + ol] = w_ro[(size_t)(ot + ol) * R_DIM + c + k];
        }
        for (int tt = 0; tt < 4; tt++) {
            const int t = t0 + tt;
            __syncthreads();  // ss reuse (and wt ready at tt=0)
            for (int idx = tid; idx < 32 * 256; idx += 256) {
                int k = idx >> 5, bb = idx & 31;
                ss[bb * 257 + k] = g_states[((size_t)t * R_DIM + c + k) * B_DIM + bb];
            }
            __syncthreads();
#pragma unroll 4
            for (int k = 0; k < 256; k++) {
                unsigned long long pv; PACK2(pv, ss[b * 257 + k]);
                const ulonglong2* wp = (const ulonglong2*)(wt + k * 68 + og * 8);
                ulonglong2 w0 = wp[0], w1 = wp[1];
                FMA2(acc[tt][0], w0.x, pv); FMA2(acc[tt][1], w0.y, pv);
                FMA2(acc[tt][2], w1.x, pv); FMA2(acc[tt][3], w1.y, pv);
            }
        }
    }

    float bo[8];
#pragma unroll
    for (int p = 0; p < 8; p++) bo[p] = b_ro[ot + og * 8 + p];

#pragma unroll
    for (int tt = 0; tt < 4; tt++) {
        const int t = t0 + tt;
#pragma unroll
        for (int p = 0; p < 4; p++) {
            unsigned int lo, hi;
            asm("mov.b64 {%0, %1}, %2;" : "=r"(lo), "=r"(hi) : "l"(acc[tt][p]));
            int o = ot + og * 8 + 2 * p;
            out[((size_t)b * T_SEQ + t) * O_DIM + o]     = __uint_as_float(lo) + bo[2 * p];
            out[((size_t)b * T_SEQ + t) * O_DIM + o + 1] = __uint_as_float(hi) + bo[2 * p + 1];
        }
    }
}

// ---------------- launch ----------------
extern "C" void kernel_launch(void* const* d_in, const int* in_sizes, int n_in,
                              void* d_out, int out_size) {
    (void)in_sizes; (void)n_in; (void)out_size;
    const float* u     = (const float*)d_in[0];  // (32, 512, 256)
    const float* state = (const float*)d_in[1];  // (32, 2048)
    const float* W_in  = (const float*)d_in[2];  // (2048, 256)
    const float* W     = (const float*)d_in[3];  // (2048, 2048)
    const float* bias  = (const float*)d_in[4];  // (2048,)
    const float* w_ro  = (const float*)d_in[5];  // (256, 2048)
    const float* b_ro  = (const float*)d_in[6];  // (256,)
    float* out = (float*)d_out;                  // (32, 512, 256)

    cudaFuncSetAttribute(uproj_kernel,   cudaFuncAttributeMaxDynamicSharedMemorySize, SMEM_GEMM);
    cudaFuncSetAttribute(readout_kernel, cudaFuncAttributeMaxDynamicSharedMemorySize, SMEM_GEMM);
    cudaFuncSetAttribute(recur_kernel,   cudaFuncAttributeMaxDynamicSharedMemorySize, SMEM_RECUR);

    s0T_kernel<<<256, 256>>>(state);
    uproj_kernel<<<dim3(T_SEQ / 8, R_DIM / 64), 256, SMEM_GEMM>>>(u, W_in, bias);
    recur_kernel<<<NB, RTH, SMEM_RECUR>>>(W);
    readout_kernel<<<dim3(T_SEQ / 4, O_DIM / 64), 256, SMEM_GEMM>>>(w_ro, b_ro, out);
}